// round 10
// baseline (speedup 1.0000x reference)
#include <cuda_runtime.h>
#include <cuda_bf16.h>

// FWHT, N = 4096, fp32, Sylvester ordering.
// e = r*256 + w*32 + lane  (r = bits 8-11, w = warp bits 5-7, lane = bits 0-4)
// Pass 1: fwht16 over r in registers (coalesced scalar load).
// Pass 2: 5 shfl.xor butterfly stages over the 5 lane bits.
// Pass 3: one smem exchange (identity layout, conflict-free both sides),
//         then 2x fwht8 over the 3 warp bits. Coalesced scalar store.
// L1 wavefronts/CTA: 128 (load) + 256 (smem) + 128 (store) = 512.

#define FWHT_N 4096

__global__ __launch_bounds__(256, 6)
void HadamardTransform_68891275428167_kernel(const float* __restrict__ x,
                                             float* __restrict__ y) {
    __shared__ float s[FWHT_N];          // 16 KB, identity layout s[e]

    const int t    = threadIdx.x;        // 0..255
    const int lane = t & 31;
    const size_t row_off = (size_t)blockIdx.x * FWHT_N;
    const float* __restrict__ xr = x + row_off;
    float* __restrict__ yr = y + row_off;

    float v[16];

    // ---- Load: v[r] = x[r*256 + t]; 16x LDG.32, 1 wf each. ----
#pragma unroll
    for (int r = 0; r < 16; r++)
        v[r] = xr[(r << 8) + t];

    // ---- Pass 1: fwht16 over r (bits 8-11). ----
#pragma unroll
    for (int h = 1; h < 16; h <<= 1) {
#pragma unroll
        for (int i = 0; i < 16; i++) {
            if ((i & h) == 0) {
                float a = v[i];
                float b = v[i + h];
                v[i]     = a + b;
                v[i + h] = a - b;
            }
        }
    }

    // ---- Pass 2: 5 shuffle-butterfly stages over lane bits 0-4. ----
    // bit=0 lane: own + partner;  bit=1 lane: partner - own.
#pragma unroll
    for (int h = 1; h <= 16; h <<= 1) {
        const float sgn = (lane & h) ? -1.0f : 1.0f;
#pragma unroll
        for (int i = 0; i < 16; i++) {
            float p = __shfl_xor_sync(0xffffffffu, v[i], h);
            v[i] = fmaf(sgn, v[i], p);
        }
    }

    // ---- Exchange: s[e] identity; both sides lane-consecutive. ----
#pragma unroll
    for (int r = 0; r < 16; r++)
        s[(r << 8) + t] = v[r];
    __syncthreads();

    // Read: reg q = (w<<1)|r0 holds e = ((wp*2+r0)<<8) + (w<<5) + lane,
    // where wp = t>>5. Lanes consecutive -> conflict-free.
    {
        const int wp = t >> 5;
#pragma unroll
        for (int q = 0; q < 16; q++) {
            const int r = (wp << 1) | (q & 1);
            const int w = q >> 1;
            v[q] = s[(r << 8) + (w << 5) + lane];
        }
    }

    // ---- Pass 3: fwht8 over w (q bits 1-3) for both r0 groups. ----
#pragma unroll
    for (int h = 2; h < 16; h <<= 1) {
#pragma unroll
        for (int i = 0; i < 16; i++) {
            if ((i & h) == 0) {
                float a = v[i];
                float b = v[i + h];
                v[i]     = a + b;
                v[i + h] = a - b;
            }
        }
    }

    // ---- Store: same e mapping as the read; 16x STG.32, 1 wf each. ----
    {
        const int wp = t >> 5;
#pragma unroll
        for (int q = 0; q < 16; q++) {
            const int r = (wp << 1) | (q & 1);
            const int w = q >> 1;
            yr[(r << 8) + (w << 5) + lane] = v[q];
        }
    }
}

extern "C" void kernel_launch(void* const* d_in, const int* in_sizes, int n_in,
                              void* d_out, int out_size) {
    const float* x = (const float*)d_in[0];
    float* y = (float*)d_out;

    const int rows = in_sizes[0] / FWHT_N;   // 16384
    HadamardTransform_68891275428167_kernel<<<rows, 256>>>(x, y);
}

// round 11
// speedup vs baseline: 1.0133x; 1.0133x over previous
#include <cuda_runtime.h>
#include <cuda_bf16.h>

// FWHT, N = 4096, fp32, Sylvester ordering.
// e = r*256 + m*16 + l  (r = e[11:8], m = e[7:4], l = e[3:0]).
// All global accesses coalesced scalar (1 wf / 128B). Three conflict-free
// smem exchanges cycle bits 11:8 -> 7:4 -> 3:0 -> 11:8 through registers.
// Wavefronts/CTA: 128 (ld) + 3*256 (smem) + 128 (st) = 1024  (R5 was 1152).

#define FWHT_N 4096
#define PITCH  272            // 272 % 32 == 16 -> parity-half separation

__device__ __forceinline__ void fwht16(float v[16]) {
#pragma unroll
    for (int h = 1; h < 16; h <<= 1) {
#pragma unroll
        for (int i = 0; i < 16; i++) {
            if ((i & h) == 0) {
                float a = v[i];
                float b = v[i + h];
                v[i]     = a + b;
                v[i + h] = a - b;
            }
        }
    }
}

__global__ __launch_bounds__(256, 8)
void HadamardTransform_68891275428167_kernel(const float* __restrict__ x,
                                             float* __restrict__ y) {
    __shared__ float s[16 * PITCH];   // 17408 B

    const int t  = threadIdx.x;       // 0..255
    const int th = t >> 4;            // high nibble of thread id
    const int tl = t & 15;            // low nibble
    const size_t row_off = (size_t)blockIdx.x * FWHT_N;
    const float* __restrict__ xr = x + row_off;
    float* __restrict__ yr = y + row_off;

    float v[16];

    // ---- Load: v[r] = x[r*256 + t]; 16x LDG.32 coalesced. thread=(m,l). ----
#pragma unroll
    for (int r = 0; r < 16; r++)
        v[r] = xr[(r << 8) + t];

    fwht16(v);   // bits 11:8

    // ---- Exchange 1: a(r,m,l) = r*PITCH + m*16 + l ----
    // Write: thread (m,l): a = r*PITCH + t.
#pragma unroll
    for (int r = 0; r < 16; r++)
        s[r * PITCH + t] = v[r];
    __syncthreads();
    // Read: thread role (r=th, l=tl): v[m] = s[r*PITCH + m*16 + l].
    {
        const float* base = s + th * PITCH + tl;
#pragma unroll
        for (int m = 0; m < 16; m++)
            v[m] = base[m << 4];
    }

    fwht16(v);   // bits 7:4

    __syncthreads();   // WAR: exchange-1 reads done before overwrite

    // ---- Exchange 2: c(r,m,l) = r*PITCH + m*16 + ((l+m)&15) ----
    // Write: thread (r=th, l=tl) holds v[m].
    {
        float* base = s + th * PITCH;
#pragma unroll
        for (int m = 0; m < 16; m++)
            base[(m << 4) + ((tl + m) & 15)] = v[m];
    }
    __syncthreads();
    // Read: thread role (r=th, m=tl): v[l] = s[c(r,m,l)].
    {
        const float* base = s + th * PITCH + (tl << 4);
#pragma unroll
        for (int l = 0; l < 16; l++)
            v[l] = base[(l + tl) & 15];
    }

    fwht16(v);   // bits 3:0

    // ---- Exchange 3: same c(); each thread writes exactly the addresses it
    // just read (same (r,m,l) set), so no barrier needed before the writes.
    {
        float* base = s + th * PITCH + (tl << 4);
#pragma unroll
        for (int l = 0; l < 16; l++)
            base[(l + tl) & 15] = v[l];
    }
    __syncthreads();
    // Read: thread role (m=th, l=tl): v[r] = s[c(r,m,l)] ; then coalesced store.
    {
        const float* base = s + (th << 4) + ((tl + th) & 15);
#pragma unroll
        for (int r = 0; r < 16; r++)
            v[r] = base[r * PITCH];
    }

    // ---- Store: y[r*256 + t]; 16x STG.32 coalesced. ----
#pragma unroll
    for (int r = 0; r < 16; r++)
        yr[(r << 8) + t] = v[r];
}

extern "C" void kernel_launch(void* const* d_in, const int* in_sizes, int n_in,
                              void* d_out, int out_size) {
    const float* x = (const float*)d_in[0];
    float* y = (float*)d_out;

    const int rows = in_sizes[0] / FWHT_N;   // 16384
    HadamardTransform_68891275428167_kernel<<<rows, 256>>>(x, y);
}

// round 12
// speedup vs baseline: 1.0252x; 1.0117x over previous
#include <cuda_runtime.h>
#include <cuda_bf16.h>

// FWHT, N = 4096, fp32, Sylvester ordering.
// e = r*256 + m*16 + l  (r = e[11:8], m = e[7:4], l = e[3:0]).
// All global accesses coalesced scalar (1 wf / 128B). Three conflict-free
// smem exchanges cycle bits 11:8 -> 7:4 -> 3:0 -> 11:8 through registers.
// Wavefronts/CTA: 128 (ld) + 3*256 (smem) + 128 (st) = 1024  (R5 was 1152).

#define FWHT_N 4096
#define PITCH  272            // 272 % 32 == 16 -> parity-half separation

__device__ __forceinline__ void fwht16(float v[16]) {
#pragma unroll
    for (int h = 1; h < 16; h <<= 1) {
#pragma unroll
        for (int i = 0; i < 16; i++) {
            if ((i & h) == 0) {
                float a = v[i];
                float b = v[i + h];
                v[i]     = a + b;
                v[i + h] = a - b;
            }
        }
    }
}

__global__ __launch_bounds__(256, 8)
void HadamardTransform_68891275428167_kernel(const float* __restrict__ x,
                                             float* __restrict__ y) {
    __shared__ float s[16 * PITCH];   // 17408 B

    const int t  = threadIdx.x;       // 0..255
    const int th = t >> 4;            // high nibble of thread id
    const int tl = t & 15;            // low nibble
    const size_t row_off = (size_t)blockIdx.x * FWHT_N;
    const float* __restrict__ xr = x + row_off;
    float* __restrict__ yr = y + row_off;

    float v[16];

    // ---- Load: v[r] = x[r*256 + t]; 16x LDG.32 coalesced. thread=(m,l). ----
#pragma unroll
    for (int r = 0; r < 16; r++)
        v[r] = xr[(r << 8) + t];

    fwht16(v);   // bits 11:8

    // ---- Exchange 1: a(r,m,l) = r*PITCH + m*16 + l ----
    // Write: thread (m,l): a = r*PITCH + t.
#pragma unroll
    for (int r = 0; r < 16; r++)
        s[r * PITCH + t] = v[r];
    __syncthreads();
    // Read: thread role (r=th, l=tl): v[m] = s[r*PITCH + m*16 + l].
    {
        const float* base = s + th * PITCH + tl;
#pragma unroll
        for (int m = 0; m < 16; m++)
            v[m] = base[m << 4];
    }

    fwht16(v);   // bits 7:4

    __syncthreads();   // WAR: exchange-1 reads done before overwrite

    // ---- Exchange 2: c(r,m,l) = r*PITCH + m*16 + ((l+m)&15) ----
    // Write: thread (r=th, l=tl) holds v[m].
    {
        float* base = s + th * PITCH;
#pragma unroll
        for (int m = 0; m < 16; m++)
            base[(m << 4) + ((tl + m) & 15)] = v[m];
    }
    __syncthreads();
    // Read: thread role (r=th, m=tl): v[l] = s[c(r,m,l)].
    {
        const float* base = s + th * PITCH + (tl << 4);
#pragma unroll
        for (int l = 0; l < 16; l++)
            v[l] = base[(l + tl) & 15];
    }

    fwht16(v);   // bits 3:0

    // ---- Exchange 3: same c(); each thread writes exactly the addresses it
    // just read (same (r,m,l) set), so no barrier needed before the writes.
    {
        float* base = s + th * PITCH + (tl << 4);
#pragma unroll
        for (int l = 0; l < 16; l++)
            base[(l + tl) & 15] = v[l];
    }
    __syncthreads();
    // Read: thread role (m=th, l=tl): v[r] = s[c(r,m,l)] ; then coalesced store.
    {
        const float* base = s + (th << 4) + ((tl + th) & 15);
#pragma unroll
        for (int r = 0; r < 16; r++)
            v[r] = base[r * PITCH];
    }

    // ---- Store: y[r*256 + t]; 16x STG.32 coalesced. ----
#pragma unroll
    for (int r = 0; r < 16; r++)
        yr[(r << 8) + t] = v[r];
}

extern "C" void kernel_launch(void* const* d_in, const int* in_sizes, int n_in,
                              void* d_out, int out_size) {
    const float* x = (const float*)d_in[0];
    float* y = (float*)d_out;

    const int rows = in_sizes[0] / FWHT_N;   // 16384
    HadamardTransform_68891275428167_kernel<<<rows, 256>>>(x, y);
}

// round 13
// speedup vs baseline: 1.1224x; 1.0948x over previous
#include <cuda_runtime.h>
#include <cuda_bf16.h>

// FWHT, N = 4096, fp32, Sylvester ordering.  H4096 = H64 (x) H64.
// One CTA (64 threads) per row; 64 regs/thread.
//   Pass 1: fwht64 over e[11:6] in registers (coalesced load).
//   One smem exchange (rotation swizzle, conflict-free scalar writes,
//   LDS.128 reads), pass 2: fwht64 over e[5:0], write-back to the same
//   addresses (no extra barrier), conflict-free gather + coalesced store.
// LSU cycles/row: 128 (ld) + 256 (xchg) + 256 (xchg2) + 128 (st) = 768
// vs 1152 for the best previous kernel.

#define FWHT_N 4096

__device__ __forceinline__ void fwht64(float v[64]) {
#pragma unroll
    for (int h = 1; h < 64; h <<= 1) {
#pragma unroll
        for (int i = 0; i < 64; i++) {
            if ((i & h) == 0) {
                float a = v[i];
                float b = v[i + h];
                v[i]     = a + b;
                v[i + h] = a - b;
            }
        }
    }
}

__global__ __launch_bounds__(64, 10)
void HadamardTransform_68891275428167_kernel(const float* __restrict__ x,
                                             float* __restrict__ y) {
    __shared__ __align__(16) float s[FWHT_N];   // 16 KB

    const int t = threadIdx.x;                  // 0..63  (= lo at load time)
    const size_t row_off = (size_t)blockIdx.x * FWHT_N;
    const float* __restrict__ xr = x + row_off;
    float* __restrict__ yr = y + row_off;

    float v[64];

    // ---- Load: v[hi] = x[hi*64 + t]; 64x LDG.32, each 1 wf (dense). ----
#pragma unroll
    for (int hi = 0; hi < 64; hi++)
        v[hi] = __ldcs(xr + (hi << 6) + t);

    fwht64(v);   // bits 11:6

    // ---- Exchange: a(hi,lo) = hi*64 + ((lo + 4*hi) & 63). ----
    // Write: thread t=lo; banks ((lo+4hi)&63)%32 distinct over lanes.
#pragma unroll
    for (int hi = 0; hi < 64; hi++)
        s[(hi << 6) + ((t + (hi << 2)) & 63)] = v[hi];
    __syncthreads();

    // Read: thread t=hi'; v[lo] = s[a(hi',lo)] as 16x LDS.128
    // (quads rotate intact: quad index (q + t) & 15; conflict-free).
    {
        const float4* sv = reinterpret_cast<const float4*>(s + (t << 6));
#pragma unroll
        for (int q = 0; q < 16; q++) {
            float4 f = sv[(q + t) & 15];
            v[4 * q + 0] = f.x;
            v[4 * q + 1] = f.y;
            v[4 * q + 2] = f.z;
            v[4 * q + 3] = f.w;
        }
    }

    fwht64(v);   // bits 5:0

    // ---- Write back to the SAME addresses this thread just read ----
    // (same-thread RMW: no barrier needed before these stores).
    {
        float4* sv = reinterpret_cast<float4*>(s + (t << 6));
#pragma unroll
        for (int q = 0; q < 16; q++)
            sv[(q + t) & 15] = make_float4(v[4 * q + 0], v[4 * q + 1],
                                           v[4 * q + 2], v[4 * q + 3]);
    }
    __syncthreads();

    // ---- Gather + coalesced store: y[hi*64 + t] = s[a(hi, t)]. ----
    // LDS banks ((t+4hi)&63)%32 distinct over lanes; STG dense 1 wf.
#pragma unroll
    for (int hi = 0; hi < 64; hi++)
        __stcs(yr + (hi << 6) + t, s[(hi << 6) + ((t + (hi << 2)) & 63)]);
}

extern "C" void kernel_launch(void* const* d_in, const int* in_sizes, int n_in,
                              void* d_out, int out_size) {
    const float* x = (const float*)d_in[0];
    float* y = (float*)d_out;

    const int rows = in_sizes[0] / FWHT_N;   // 16384
    HadamardTransform_68891275428167_kernel<<<rows, 64>>>(x, y);
}